// round 14
// baseline (speedup 1.0000x reference)
#include <cuda_runtime.h>
#include <cstdint>
#include <math.h>

#define B_   64
#define S_   512
#define I_   256
#define H_   512
#define G4H  2048
#define GRID 128
#define NTH  512
#define HCW  132          // h chunk row width (128 + 4 pad)

typedef unsigned long long ull;

// SMEM float counts (recurrent kernel)
#define F_U   (512*16)        // U, layout [(k>>2)*64 + gate*16 + (k&3)*4 + jl]
#define F_H   (4*64*HCW)      // 4 chunks x [64][132]
#define F_XP  (4*64*16)       // 4-slot xp ring [64][16]
#define F_P   (128*20)        // partials [kh*64+b][20] (stride 20, conflict-free)
#define F_HO  (64*4)          // staged h output
#define SMEM_FLOATS (F_U + F_H + F_XP + F_P + F_HO)
#define SMEM_BYTES  (SMEM_FLOATS*4 + 128)

// ---------------- static device scratch ----------------
__device__ __align__(256) float g_xp[(size_t)S_ * GRID * B_ * 16]; // [t][blk][b][16]
__device__ __align__(256) float g_h[4 * B_ * HCW];                 // [chunk][b][132]
__device__ unsigned g_bar_cnt = 0;
__device__ volatile unsigned g_bar_sense = 0;

// ---------------- PTX helpers ----------------
__device__ __forceinline__ unsigned sm2u(const void* p) {
    unsigned a;
    asm("{ .reg .u64 t; cvta.to.shared.u64 t, %1; cvt.u32.u64 %0, t; }" : "=r"(a) : "l"(p));
    return a;
}
__device__ __forceinline__ void mbar_init(unsigned a, unsigned c) {
    asm volatile("mbarrier.init.shared.b64 [%0], %1;" :: "r"(a), "r"(c) : "memory");
}
__device__ __forceinline__ void mbar_arrive_expect(unsigned a, unsigned bytes) {
    asm volatile("mbarrier.arrive.expect_tx.shared.b64 _, [%0], %1;"
                 :: "r"(a), "r"(bytes) : "memory");
}
__device__ __forceinline__ void bulk_g2s(unsigned dst, const void* src,
                                         unsigned bytes, unsigned mbar) {
    asm volatile("cp.async.bulk.shared::cluster.global.mbarrier::complete_tx::bytes "
                 "[%0], [%1], %2, [%3];"
                 :: "r"(dst), "l"(src), "r"(bytes), "r"(mbar) : "memory");
}
__device__ __forceinline__ void mbar_wait(unsigned a, unsigned ph) {
    unsigned done = 0;
    while (!done) {
        asm volatile("{ .reg .pred p; "
                     "mbarrier.try_wait.parity.acquire.cta.shared::cta.b64 p, [%1], %2, 0x989680; "
                     "selp.b32 %0, 1, 0, p; }"
                     : "=r"(done) : "r"(a), "r"(ph) : "memory");
    }
}
__device__ __forceinline__ void fma2(ull& acc, ull a, ull b) {
    asm("fma.rn.f32x2 %0, %1, %2, %0;" : "+l"(acc) : "l"(a), "l"(b));
}
__device__ __forceinline__ ull dupf(float v) {
    ull r; asm("mov.b64 %0, {%1, %1};" : "=l"(r) : "f"(v)); return r;
}
__device__ __forceinline__ float rcp_(float x) {
    float y; asm("rcp.approx.f32 %0, %1;" : "=f"(y) : "f"(x)); return y;
}
__device__ __forceinline__ float sig_(float x)  { return rcp_(1.0f + __expf(-x)); }
__device__ __forceinline__ float tanh_(float x) { return fmaf(2.0f, rcp_(1.0f + __expf(-2.0f * x)), -1.0f); }

// 4 k-steps, 4 cols; weights are 64B contiguous per thread (2 dedup wavefronts/warp)
__device__ __forceinline__ void dot4(const float* __restrict__ ab,
                                     const float* __restrict__ wp,
                                     ull& a01, ull& a23) {
    float4 h4 = *reinterpret_cast<const float4*>(ab);
    ulonglong2 w0 = *reinterpret_cast<const ulonglong2*>(wp);
    ulonglong2 w1 = *reinterpret_cast<const ulonglong2*>(wp + 4);
    ulonglong2 w2 = *reinterpret_cast<const ulonglong2*>(wp + 8);
    ulonglong2 w3 = *reinterpret_cast<const ulonglong2*>(wp + 12);
    ull h;
    h = dupf(h4.x); fma2(a01, h, w0.x); fma2(a23, h, w0.y);
    h = dupf(h4.y); fma2(a01, h, w1.x); fma2(a23, h, w1.y);
    h = dupf(h4.z); fma2(a01, h, w2.x); fma2(a23, h, w2.y);
    h = dupf(h4.w); fma2(a01, h, w3.x); fma2(a23, h, w3.y);
}

// ---------------- init ----------------
__global__ void k_init() {
    int i = blockIdx.x * blockDim.x + threadIdx.x;
    if (i < 4 * B_ * HCW) g_h[i] = 0.0f;
}

// ---------------- x-projection GEMM (f32x2): g_xp = x @ W + bias ----------------
__global__ void __launch_bounds__(256, 2)
k_xproj(const float* __restrict__ x, const float* __restrict__ W,
        const float* __restrict__ bias) {
    __shared__ float As[16][132];
    __shared__ float Bs[16][128];
    const int tid = threadIdx.x;
    const int tx = tid & 15, ty = tid >> 4;
    const int m0 = blockIdx.x * 128;
    const int n0 = blockIdx.y * 128;

    ull acc2[8][4];
#pragma unroll
    for (int r = 0; r < 8; ++r)
#pragma unroll
        for (int c = 0; c < 4; ++c) acc2[r][c] = 0ull;

    for (int k0 = 0; k0 < I_; k0 += 16) {
        __syncthreads();
#pragma unroll
        for (int i = tid; i < 512; i += 256) {
            int r = i >> 2, g = i & 3;
            float4 v = *reinterpret_cast<const float4*>(
                x + (size_t)(m0 + r) * I_ + k0 + g * 4);
            As[g * 4 + 0][r] = v.x; As[g * 4 + 1][r] = v.y;
            As[g * 4 + 2][r] = v.z; As[g * 4 + 3][r] = v.w;
        }
#pragma unroll
        for (int i = tid; i < 512; i += 256) {
            int kk = i >> 5, g = i & 31;
            *reinterpret_cast<float4*>(&Bs[kk][g * 4]) =
                *reinterpret_cast<const float4*>(W + (size_t)(k0 + kk) * G4H + n0 + g * 4);
        }
        __syncthreads();
#pragma unroll
        for (int kk = 0; kk < 16; ++kk) {
            float a[8];
            *reinterpret_cast<float4*>(a)     = *reinterpret_cast<float4*>(&As[kk][ty * 8]);
            *reinterpret_cast<float4*>(a + 4) = *reinterpret_cast<float4*>(&As[kk][ty * 8 + 4]);
            ull bw[4];
            {
                ulonglong2 p0 = *reinterpret_cast<ulonglong2*>(&Bs[kk][tx * 4]);
                ulonglong2 p1 = *reinterpret_cast<ulonglong2*>(&Bs[kk][tx * 4 + 64]);
                bw[0] = p0.x; bw[1] = p0.y; bw[2] = p1.x; bw[3] = p1.y;
            }
#pragma unroll
            for (int r = 0; r < 8; ++r) {
                ull ha = dupf(a[r]);
#pragma unroll
                for (int c = 0; c < 4; ++c) fma2(acc2[r][c], ha, bw[c]);
            }
        }
    }

    // epilogue: +bias, scatter to g_xp[t][cg][b][q*4+jl]
    const int b  = m0 >> 9;
    const int tb = (m0 & 511) + ty * 8;
    float4 bias0 = *reinterpret_cast<const float4*>(bias + n0 + tx * 4);
    float4 bias1 = *reinterpret_cast<const float4*>(bias + n0 + tx * 4 + 64);
#pragma unroll
    for (int r = 0; r < 8; ++r) {
        int t = tb + r;
#pragma unroll
        for (int grp = 0; grp < 2; ++grp) {
            int n  = n0 + tx * 4 + grp * 64;
            int q  = n >> 9;
            int cg = (n & 511) >> 2;
            float f0, f1, f2, f3;
            asm("mov.b64 {%0, %1}, %2;" : "=f"(f0), "=f"(f1) : "l"(acc2[r][grp * 2 + 0]));
            asm("mov.b64 {%0, %1}, %2;" : "=f"(f2), "=f"(f3) : "l"(acc2[r][grp * 2 + 1]));
            float4 v;
            v.x = f0 + (grp ? bias1.x : bias0.x);
            v.y = f1 + (grp ? bias1.y : bias0.y);
            v.z = f2 + (grp ? bias1.z : bias0.z);
            v.w = f3 + (grp ? bias1.w : bias0.w);
            *reinterpret_cast<float4*>(
                g_xp + (((size_t)t * GRID + cg) * B_ + b) * 16 + q * 4) = v;
        }
    }
}

// ---------------- persistent recurrent kernel (512 threads, K-split) ----------------
__global__ void __launch_bounds__(NTH, 1)
k_lstm(const float* __restrict__ U, float* __restrict__ out) {
    extern __shared__ float sm[];
    float* sU   = sm;                 // F_U
    float* sH   = sU + F_U;           // F_H
    float* sXP  = sH + F_H;           // F_XP
    float* sP   = sXP + F_XP;         // F_P
    float* sHo  = sP + F_P;           // F_HO
    unsigned long long* mb = reinterpret_cast<unsigned long long*>(sHo + F_HO);
    const unsigned mbH0  = sm2u(mb);        // +8*c, c=0..3
    const unsigned mbXP0 = sm2u(mb + 4);    // +8*s, s=0..3
    const unsigned sH_u  = sm2u(sH);
    const unsigned sXP_u = sm2u(sXP);

    const int tid = threadIdx.x;
    const int blk = blockIdx.x;
    const int kh  = tid >> 8;         // K half
    const int r   = tid & 255;
    const int b   = r >> 2;           // batch 0..63
    const int cq  = r & 3;            // gate 0..3
    // update mapping (tid < 256)
    const int bu  = r >> 2;
    const int jl  = r & 3;
    const int hcol = blk * 4 + jl;
    float c_state = 0.0f;

    // ---- prologue ----
    if (tid == 0) {
#pragma unroll
        for (int i = 0; i < 8; ++i) mbar_init(mbH0 + i * 8, 1);
        asm volatile("fence.proxy.async.shared::cta;" ::: "memory");
    }
    // U -> SMEM, layout [(k>>2)*64 + q*16 + (k&3)*4]
    for (int i = tid; i < 512 * 4; i += NTH) {
        int k = i >> 2, q = i & 3;
        float4 w = *reinterpret_cast<const float4*>(
            U + (size_t)k * G4H + q * H_ + blk * 4);
        *reinterpret_cast<float4*>(sU + (k >> 2) * 64 + q * 16 + (k & 3) * 4) = w;
    }
    __syncthreads();
    if (tid == 0) {   // prefetch xp slots t=0..3
#pragma unroll
        for (int s = 0; s < 4; ++s) {
            mbar_arrive_expect(mbXP0 + s * 8, 4096);
            bulk_g2s(sXP_u + (unsigned)(s * 4096),
                     g_xp + ((size_t)s * GRID + blk) * (B_ * 16), 4096, mbXP0 + s * 8);
        }
    }

    const int c_first  = kh * 2 + (blk & 1);
    const int c_second = kh * 2 + ((blk & 1) ^ 1);

    for (int t = 0; t < S_; ++t) {
        // ---- issue 4 h-chunk TMAs, per-CTA rotated order (L2 spread) ----
        if (tid == 0) {
#pragma unroll
            for (int i = 0; i < 4; ++i) {
                int c = (blk + i) & 3;
                mbar_arrive_expect(mbH0 + (unsigned)(c * 8), 64 * HCW * 4);
                bulk_g2s(sH_u + (unsigned)(c * 64 * HCW * 4),
                         g_h + c * (64 * HCW), 64 * HCW * 4, mbH0 + (unsigned)(c * 8));
            }
        }

        // ---- accumulator init ----
        const int s = t & 3;
        ull a01, a23;
        if (kh == 0) {
            mbar_wait(mbXP0 + (unsigned)(s * 8), (unsigned)((t >> 2) & 1));
            float4 xin = *reinterpret_cast<const float4*>(
                sXP + s * (64 * 16) + b * 16 + cq * 4);
            asm("mov.b64 %0, {%1, %2};" : "=l"(a01) : "f"(xin.x), "f"(xin.y));
            asm("mov.b64 %0, {%1, %2};" : "=l"(a23) : "f"(xin.z), "f"(xin.w));
        } else {
            a01 = 0ull; a23 = 0ull;
        }

        // ---- this half's 2 k-chunks of 128 ----
#pragma unroll
        for (int cc = 0; cc < 2; ++cc) {
            const int c = cc ? c_second : c_first;
            mbar_wait(mbH0 + (unsigned)(c * 8), (unsigned)(t & 1));
            const float* hb = sH + c * (64 * HCW) + b * HCW;
            const float* wb = sU + c * 2048 + cq * 16;
#pragma unroll 4
            for (int kk = 0; kk < 128; kk += 4)
                dot4(hb + kk, wb + (kk << 4), a01, a23);
        }

        // ---- write partials ----
        {
            float4 pv;
            asm("mov.b64 {%0, %1}, %2;" : "=f"(pv.x), "=f"(pv.y) : "l"(a01));
            asm("mov.b64 {%0, %1}, %2;" : "=f"(pv.z), "=f"(pv.w) : "l"(a23));
            *reinterpret_cast<float4*>(sP + (kh * 64 + b) * 20 + cq * 4) = pv;
        }
        __syncthreads();

        // xp refill (sXP slot s consumed)
        if (tid == 0 && t + 4 < S_) {
            mbar_arrive_expect(mbXP0 + (unsigned)(s * 8), 4096);
            bulk_g2s(sXP_u + (unsigned)(s * 4096),
                     g_xp + ((size_t)(t + 4) * GRID + blk) * (B_ * 16), 4096,
                     mbXP0 + (unsigned)(s * 8));
        }

        // ---- cell update (first 256 threads) ----
        if (tid < 256) {
            const float* p0 = sP + bu * 20 + jl;
            const float* p1 = sP + (64 + bu) * 20 + jl;
            float gi = p0[0]  + p1[0];
            float gf = p0[4]  + p1[4];
            float gg = p0[8]  + p1[8];
            float go = p0[12] + p1[12];
            float iv = sig_(gi);
            float fv = sig_(gf);
            float gt = tanh_(gg);
            float ov = sig_(go);
            c_state = fv * c_state + iv * gt;
            float hv = ov * tanh_(c_state);
            sHo[bu * 4 + jl] = hv;
            if (t == S_ - 1) {
                size_t base = (size_t)B_ * S_ * H_;
                out[base + (size_t)bu * H_ + hcol] = hv;
                out[base + (size_t)B_ * H_ + (size_t)bu * H_ + hcol] = c_state;
            }
        }
        __syncthreads();

        // ---- coalesced h/out writes (64 threads, STG.128) ----
        if (tid < 64) {
            float4 hv4 = *reinterpret_cast<float4*>(sHo + tid * 4);
            *reinterpret_cast<float4*>(
                out + ((size_t)tid * S_ + t) * H_ + blk * 4) = hv4;
            *reinterpret_cast<float4*>(
                g_h + ((blk >> 5) * 64 + tid) * HCW + (blk & 31) * 4) = hv4;
        }
        __syncthreads();

        // ---- grid barrier ----
        if (tid == 0) {
            __threadfence();
            unsigned want = (unsigned)((t & 1) ^ 1);
            if (atomicAdd(&g_bar_cnt, 1u) == GRID - 1) {
                atomicExch(&g_bar_cnt, 0u);
                __threadfence();
                g_bar_sense = want;
            } else {
                while (g_bar_sense != want) { }
            }
            __threadfence();
        }
        __syncthreads();
    }
}

// ---------------- launch ----------------
extern "C" void kernel_launch(void* const* d_in, const int* in_sizes, int n_in,
                              void* d_out, int out_size) {
    const float* x = nullptr; const float* W = nullptr;
    const float* U = nullptr; const float* bias = nullptr;
    for (int i = 0; i < n_in; ++i) {
        switch (in_sizes[i]) {
            case B_ * S_ * I_: x    = (const float*)d_in[i]; break;
            case I_ * G4H:     W    = (const float*)d_in[i]; break;
            case H_ * G4H:     U    = (const float*)d_in[i]; break;
            case G4H:          bias = (const float*)d_in[i]; break;
            default: break;
        }
    }
    if (!x && n_in > 0)    x    = (const float*)d_in[0];
    if (!W && n_in > 1)    W    = (const float*)d_in[1];
    if (!U && n_in > 2)    U    = (const float*)d_in[2];
    if (!bias && n_in > 3) bias = (const float*)d_in[3];

    cudaFuncSetAttribute(k_lstm, cudaFuncAttributeMaxDynamicSharedMemorySize,
                         SMEM_BYTES);
    k_init<<<(4 * B_ * HCW + 255) / 256, 256>>>();
    k_xproj<<<dim3((B_ * S_) / 128, G4H / 128), 256>>>(x, W, bias);
    k_lstm<<<GRID, NTH, SMEM_BYTES>>>(U, (float*)d_out);
}

// round 15
// speedup vs baseline: 1.6856x; 1.6856x over previous
#include <cuda_runtime.h>
#include <cstdint>
#include <math.h>

#define B_   64
#define S_   512
#define I_   256
#define H_   512
#define G4H  2048
#define GRID 128
#define NTH  512
#define HCW  132          // h chunk row width (128 + 4 pad)

typedef unsigned long long ull;

// SMEM float counts (recurrent kernel)
#define F_U   (512*16)        // U weights, layout [k*16 + gate*4 + jl] (conflict-free)
#define F_H   (4*64*HCW)      // 4 chunks x [64][132]
#define F_XP  (4*64*16)       // 4-slot xp ring [64][16]
#define F_P   (128*20)        // partials [kh*64+b][20]
#define F_HO  (64*4)          // staged h output
#define SMEM_FLOATS (F_U + F_H + F_XP + F_P + F_HO)
#define SMEM_BYTES  (SMEM_FLOATS*4 + 128)

// ---------------- static device scratch ----------------
__device__ __align__(256) float g_xp[(size_t)S_ * GRID * B_ * 16]; // [t][blk][b][16]
__device__ __align__(256) float g_h[4 * B_ * HCW];                 // [chunk][b][132]
__device__ unsigned g_cnt;                                         // monotonic barrier ctr

// ---------------- PTX helpers ----------------
__device__ __forceinline__ unsigned sm2u(const void* p) {
    unsigned a;
    asm("{ .reg .u64 t; cvta.to.shared.u64 t, %1; cvt.u32.u64 %0, t; }" : "=r"(a) : "l"(p));
    return a;
}
__device__ __forceinline__ void mbar_init(unsigned a, unsigned c) {
    asm volatile("mbarrier.init.shared.b64 [%0], %1;" :: "r"(a), "r"(c) : "memory");
}
__device__ __forceinline__ void mbar_arrive_expect(unsigned a, unsigned bytes) {
    asm volatile("mbarrier.arrive.expect_tx.shared.b64 _, [%0], %1;"
                 :: "r"(a), "r"(bytes) : "memory");
}
__device__ __forceinline__ void bulk_g2s(unsigned dst, const void* src,
                                         unsigned bytes, unsigned mbar) {
    asm volatile("cp.async.bulk.shared::cluster.global.mbarrier::complete_tx::bytes "
                 "[%0], [%1], %2, [%3];"
                 :: "r"(dst), "l"(src), "r"(bytes), "r"(mbar) : "memory");
}
__device__ __forceinline__ void mbar_wait(unsigned a, unsigned ph) {
    unsigned done = 0;
    while (!done) {
        asm volatile("{ .reg .pred p; "
                     "mbarrier.try_wait.parity.acquire.cta.shared::cta.b64 p, [%1], %2, 0x989680; "
                     "selp.b32 %0, 1, 0, p; }"
                     : "=r"(done) : "r"(a), "r"(ph) : "memory");
    }
}
__device__ __forceinline__ void fma2(ull& acc, ull a, ull b) {
    asm("fma.rn.f32x2 %0, %1, %2, %0;" : "+l"(acc) : "l"(a), "l"(b));
}
__device__ __forceinline__ ull dupf(float v) {
    ull r; asm("mov.b64 %0, {%1, %1};" : "=l"(r) : "f"(v)); return r;
}
__device__ __forceinline__ float rcp_(float x) {
    float y; asm("rcp.approx.f32 %0, %1;" : "=f"(y) : "f"(x)); return y;
}
__device__ __forceinline__ float sig_(float x)  { return rcp_(1.0f + __expf(-x)); }
__device__ __forceinline__ float tanh_(float x) { return fmaf(2.0f, rcp_(1.0f + __expf(-2.0f * x)), -1.0f); }

// 4 k-steps, 4 cols. Weight LDS.128: 4 gates x 16B = one contiguous 64B line
// per k-group -> broadcast-dedup, conflict-free (R13 layout).
__device__ __forceinline__ void dot4(const float* __restrict__ ab,
                                     const float* __restrict__ wu,
                                     ull& a01, ull& a23) {
    float4 h4 = *reinterpret_cast<const float4*>(ab);
#pragma unroll
    for (int j = 0; j < 4; ++j) {
        ull h = dupf((&h4.x)[j]);
        ulonglong2 w = *reinterpret_cast<const ulonglong2*>(wu + j * 16);
        fma2(a01, h, w.x);
        fma2(a23, h, w.y);
    }
}

// ---------------- init: zero h state, reset barrier counter ----------------
__global__ void k_init() {
    int i = blockIdx.x * blockDim.x + threadIdx.x;
    if (i < 4 * B_ * HCW) g_h[i] = 0.0f;
    if (i == 0) g_cnt = 0u;
}

// ---------------- x-projection GEMM (f32x2): g_xp = x @ W + bias ----------------
__global__ void __launch_bounds__(256, 2)
k_xproj(const float* __restrict__ x, const float* __restrict__ W,
        const float* __restrict__ bias) {
    __shared__ float As[16][132];
    __shared__ float Bs[16][128];
    const int tid = threadIdx.x;
    const int tx = tid & 15, ty = tid >> 4;
    const int m0 = blockIdx.x * 128;
    const int n0 = blockIdx.y * 128;

    ull acc2[8][4];
#pragma unroll
    for (int r = 0; r < 8; ++r)
#pragma unroll
        for (int c = 0; c < 4; ++c) acc2[r][c] = 0ull;

    for (int k0 = 0; k0 < I_; k0 += 16) {
        __syncthreads();
#pragma unroll
        for (int i = tid; i < 512; i += 256) {
            int r = i >> 2, g = i & 3;
            float4 v = *reinterpret_cast<const float4*>(
                x + (size_t)(m0 + r) * I_ + k0 + g * 4);
            As[g * 4 + 0][r] = v.x; As[g * 4 + 1][r] = v.y;
            As[g * 4 + 2][r] = v.z; As[g * 4 + 3][r] = v.w;
        }
#pragma unroll
        for (int i = tid; i < 512; i += 256) {
            int kk = i >> 5, g = i & 31;
            *reinterpret_cast<float4*>(&Bs[kk][g * 4]) =
                *reinterpret_cast<const float4*>(W + (size_t)(k0 + kk) * G4H + n0 + g * 4);
        }
        __syncthreads();
#pragma unroll
        for (int kk = 0; kk < 16; ++kk) {
            float a[8];
            *reinterpret_cast<float4*>(a)     = *reinterpret_cast<float4*>(&As[kk][ty * 8]);
            *reinterpret_cast<float4*>(a + 4) = *reinterpret_cast<float4*>(&As[kk][ty * 8 + 4]);
            ull bw[4];
            {
                ulonglong2 p0 = *reinterpret_cast<ulonglong2*>(&Bs[kk][tx * 4]);
                ulonglong2 p1 = *reinterpret_cast<ulonglong2*>(&Bs[kk][tx * 4 + 64]);
                bw[0] = p0.x; bw[1] = p0.y; bw[2] = p1.x; bw[3] = p1.y;
            }
#pragma unroll
            for (int r = 0; r < 8; ++r) {
                ull ha = dupf(a[r]);
#pragma unroll
                for (int c = 0; c < 4; ++c) fma2(acc2[r][c], ha, bw[c]);
            }
        }
    }

    const int b  = m0 >> 9;
    const int tb = (m0 & 511) + ty * 8;
    float4 bias0 = *reinterpret_cast<const float4*>(bias + n0 + tx * 4);
    float4 bias1 = *reinterpret_cast<const float4*>(bias + n0 + tx * 4 + 64);
#pragma unroll
    for (int r = 0; r < 8; ++r) {
        int t = tb + r;
#pragma unroll
        for (int grp = 0; grp < 2; ++grp) {
            int n  = n0 + tx * 4 + grp * 64;
            int q  = n >> 9;
            int cg = (n & 511) >> 2;
            float f0, f1, f2, f3;
            asm("mov.b64 {%0, %1}, %2;" : "=f"(f0), "=f"(f1) : "l"(acc2[r][grp * 2 + 0]));
            asm("mov.b64 {%0, %1}, %2;" : "=f"(f2), "=f"(f3) : "l"(acc2[r][grp * 2 + 1]));
            float4 v;
            v.x = f0 + (grp ? bias1.x : bias0.x);
            v.y = f1 + (grp ? bias1.y : bias0.y);
            v.z = f2 + (grp ? bias1.z : bias0.z);
            v.w = f3 + (grp ? bias1.w : bias0.w);
            *reinterpret_cast<float4*>(
                g_xp + (((size_t)t * GRID + cg) * B_ + b) * 16 + q * 4) = v;
        }
    }
}

// ---------------- persistent recurrent kernel (512 threads, K-split) ----------------
__global__ void __launch_bounds__(NTH, 1)
k_lstm(const float* __restrict__ U, float* __restrict__ out) {
    extern __shared__ float sm[];
    float* sU   = sm;                 // [512][16], layout k*16 + gate*4
    float* sH   = sU + F_U;           // 4 x [64][132]
    float* sXP  = sH + F_H;           // 4 x [64][16]
    float* sP   = sXP + F_XP;         // [128][20]
    float* sHo  = sP + F_P;           // [64][4]
    unsigned long long* mb = reinterpret_cast<unsigned long long*>(sHo + F_HO);
    const unsigned mbH0  = sm2u(mb);        // +8*c, c=0..3
    const unsigned mbXP0 = sm2u(mb + 4);    // +8*s, s=0..3
    const unsigned sH_u  = sm2u(sH);
    const unsigned sXP_u = sm2u(sXP);

    const int tid = threadIdx.x;
    const int blk = blockIdx.x;
    const int kh  = tid >> 8;         // K half: 0 -> chunks {0,1}, 1 -> {2,3}
    const int r   = tid & 255;
    const int b   = r >> 2;           // batch 0..63
    const int cq  = r & 3;            // gate 0..3
    const int bu  = r >> 2;           // update mapping (tid < 256)
    const int jl  = r & 3;
    const int hcol = blk * 4 + jl;
    float c_state = 0.0f;

    // ---- prologue ----
    if (tid == 0) {
#pragma unroll
        for (int i = 0; i < 8; ++i) mbar_init(mbH0 + i * 8, 1);
        asm volatile("fence.proxy.async.shared::cta;" ::: "memory");
    }
    // U -> SMEM once: sU[k*16 + q*4 + j] = U[k][q*512 + blk*4 + j]
    for (int i = tid; i < 512 * 4; i += NTH) {
        int k = i >> 2, q = i & 3;
        float4 w = *reinterpret_cast<const float4*>(
            U + (size_t)k * G4H + q * H_ + blk * 4);
        *reinterpret_cast<float4*>(sU + k * 16 + q * 4) = w;
    }
    __syncthreads();
    if (tid == 0) {   // prefetch xp slots t=0..3
#pragma unroll
        for (int s = 0; s < 4; ++s) {
            mbar_arrive_expect(mbXP0 + s * 8, 4096);
            bulk_g2s(sXP_u + (unsigned)(s * 4096),
                     g_xp + ((size_t)s * GRID + blk) * (B_ * 16), 4096, mbXP0 + s * 8);
        }
    }

    const int c_first  = kh * 2 + (blk & 1);
    const int c_second = kh * 2 + ((blk & 1) ^ 1);

    for (int t = 0; t < S_; ++t) {
        // ---- issue 4 h-chunk TMAs, per-CTA rotated order (spread L2 demand) ----
        if (tid == 0) {
#pragma unroll
            for (int i = 0; i < 4; ++i) {
                int c = (blk + i) & 3;
                mbar_arrive_expect(mbH0 + (unsigned)(c * 8), 64 * HCW * 4);
                bulk_g2s(sH_u + (unsigned)(c * 64 * HCW * 4),
                         g_h + c * (64 * HCW), 64 * HCW * 4, mbH0 + (unsigned)(c * 8));
            }
        }

        // ---- accumulator init ----
        const int s = t & 3;
        ull a01, a23;
        if (kh == 0) {
            mbar_wait(mbXP0 + (unsigned)(s * 8), (unsigned)((t >> 2) & 1));
            float4 xin = *reinterpret_cast<const float4*>(
                sXP + s * (64 * 16) + b * 16 + cq * 4);
            asm("mov.b64 %0, {%1, %2};" : "=l"(a01) : "f"(xin.x), "f"(xin.y));
            asm("mov.b64 %0, {%1, %2};" : "=l"(a23) : "f"(xin.z), "f"(xin.w));
        } else {
            a01 = 0ull; a23 = 0ull;
        }

        // ---- this half's 2 k-chunks of 128 ----
#pragma unroll
        for (int cc = 0; cc < 2; ++cc) {
            const int c = cc ? c_second : c_first;
            mbar_wait(mbH0 + (unsigned)(c * 8), (unsigned)(t & 1));
            const float* hb = sH + c * (64 * HCW) + b * HCW;
            const float* wb = sU + (c * 128) * 16 + cq * 4;
#pragma unroll 4
            for (int kk = 0; kk < 128; kk += 4)
                dot4(hb + kk, wb + kk * 16, a01, a23);
        }

        // ---- write partials ----
        {
            float4 pv;
            asm("mov.b64 {%0, %1}, %2;" : "=f"(pv.x), "=f"(pv.y) : "l"(a01));
            asm("mov.b64 {%0, %1}, %2;" : "=f"(pv.z), "=f"(pv.w) : "l"(a23));
            *reinterpret_cast<float4*>(sP + (kh * 64 + b) * 20 + cq * 4) = pv;
        }
        __syncthreads();

        // xp refill (slot s consumed by all kh=0 threads)
        if (tid == 0 && t + 4 < S_) {
            mbar_arrive_expect(mbXP0 + (unsigned)(s * 8), 4096);
            bulk_g2s(sXP_u + (unsigned)(s * 4096),
                     g_xp + ((size_t)(t + 4) * GRID + blk) * (B_ * 16), 4096,
                     mbXP0 + (unsigned)(s * 8));
        }

        // ---- cell update (first 256 threads) ----
        if (tid < 256) {
            const float* p0 = sP + bu * 20 + jl;
            const float* p1 = sP + (64 + bu) * 20 + jl;
            float gi = p0[0]  + p1[0];
            float gf = p0[4]  + p1[4];
            float gg = p0[8]  + p1[8];
            float go = p0[12] + p1[12];
            float iv = sig_(gi);
            float fv = sig_(gf);
            float gt = tanh_(gg);
            float ov = sig_(go);
            c_state = fv * c_state + iv * gt;
            float hv = ov * tanh_(c_state);
            sHo[bu * 4 + jl] = hv;
            if (t == S_ - 1) {
                size_t base = (size_t)B_ * S_ * H_;
                out[base + (size_t)bu * H_ + hcol] = hv;
                out[base + (size_t)B_ * H_ + (size_t)bu * H_ + hcol] = c_state;
            }
        }
        __syncthreads();

        // ---- coalesced h/out writes (64 threads, STG.128) ----
        if (tid < 64) {
            float4 hv4 = *reinterpret_cast<float4*>(sHo + tid * 4);
            *reinterpret_cast<float4*>(
                out + ((size_t)tid * S_ + t) * H_ + blk * 4) = hv4;
            *reinterpret_cast<float4*>(
                g_h + ((blk >> 5) * 64 + tid) * HCW + (blk & 31) * 4) = hv4;
        }
        __syncthreads();

        // ---- grid barrier: REDG (0.854 cy/op) + monotonic acquire-poll ----
        if (tid == 0) {
            __threadfence();
            asm volatile("red.release.gpu.global.add.u32 [%0], %1;"
                         :: "l"(&g_cnt), "r"(1u) : "memory");
            unsigned target = (unsigned)(t + 1) * (unsigned)GRID;
            unsigned v;
            do {
                asm volatile("ld.acquire.gpu.global.u32 %0, [%1];"
                             : "=r"(v) : "l"(&g_cnt) : "memory");
            } while (v < target);
        }
        __syncthreads();
    }
}

// ---------------- launch ----------------
extern "C" void kernel_launch(void* const* d_in, const int* in_sizes, int n_in,
                              void* d_out, int out_size) {
    const float* x = nullptr; const float* W = nullptr;
    const float* U = nullptr; const float* bias = nullptr;
    for (int i = 0; i < n_in; ++i) {
        switch (in_sizes[i]) {
            case B_ * S_ * I_: x    = (const float*)d_in[i]; break;
            case I_ * G4H:     W    = (const float*)d_in[i]; break;
            case H_ * G4H:     U    = (const float*)d_in[i]; break;
            case G4H:          bias = (const float*)d_in[i]; break;
            default: break;
        }
    }
    if (!x && n_in > 0)    x    = (const float*)d_in[0];
    if (!W && n_in > 1)    W    = (const float*)d_in[1];
    if (!U && n_in > 2)    U    = (const float*)d_in[2];
    if (!bias && n_in > 3) bias = (const float*)d_in[3];

    cudaFuncSetAttribute(k_lstm, cudaFuncAttributeMaxDynamicSharedMemorySize,
                         SMEM_BYTES);
    k_init<<<(4 * B_ * HCW + 255) / 256, 256>>>();
    k_xproj<<<dim3((B_ * S_) / 128, G4H / 128), 256>>>(x, W, bias);
    k_lstm<<<GRID, NTH, SMEM_BYTES>>>(U, (float*)d_out);
}